// round 2
// baseline (speedup 1.0000x reference)
#include <cuda_runtime.h>
#include <cuda_bf16.h>

// DynamicDilationUnfold: B=4, C=64, H=W=128, G=4, Cg=16, K=3, pad=1, stride=1,
// Ho=Wo=128. Output (B, C*K*K, Ho*Wo) fp32.
//
// Separable bilinear: per-pixel precompute 3 (row index pair, masked h-weights)
// and 3 (col index pair, masked w-weights); reuse across 16 channels x 9 taps.

#define B_  4
#define C_  64
#define H_  128
#define W_  128
#define G_  4
#define CG_ 16
#define K_  3
#define HW_ (H_ * W_)      // 16384
#define HOWO_ (H_ * W_)    // Ho*Wo = 16384

__global__ __launch_bounds__(128, 8)
void ddunfold_kernel(const float* __restrict__ x,
                     const float* __restrict__ dmap,
                     float* __restrict__ out)
{
    const int wo = threadIdx.x;          // 0..127
    const int ho = blockIdx.x;           // 0..127
    const int g  = blockIdx.y;           // 0..3
    const int b  = blockIdx.z;           // 0..3

    const float d = dmap[((b * G_ + g) * H_ + ho) * W_ + wo];

    // ---- per-pixel separable precompute ----
    float ah0[K_], ah1[K_], bw0[K_], bw1[K_];
    int   h0c[K_], h1c[K_], w0c[K_], w1c[K_];

    #pragma unroll
    for (int k = 0; k < K_; k++) {
        // h axis
        {
            const float p  = (float)(ho - 1) + (float)k * d;
            const float f0 = floorf(p);
            const float l  = p - f0;
            const bool  v0 = (f0 >= 0.0f)  && (f0 <= (float)(H_ - 1));
            const bool  v1 = (f0 >= -1.0f) && (f0 <= (float)(H_ - 2));
            ah0[k] = v0 ? (1.0f - l) : 0.0f;
            ah1[k] = v1 ? l : 0.0f;
            const int i0 = (int)f0;
            h0c[k] = min(max(i0,     0), H_ - 1);
            h1c[k] = min(max(i0 + 1, 0), H_ - 1);
        }
        // w axis
        {
            const float p  = (float)(wo - 1) + (float)k * d;
            const float f0 = floorf(p);
            const float l  = p - f0;
            const bool  v0 = (f0 >= 0.0f)  && (f0 <= (float)(W_ - 1));
            const bool  v1 = (f0 >= -1.0f) && (f0 <= (float)(W_ - 2));
            bw0[k] = v0 ? (1.0f - l) : 0.0f;
            bw1[k] = v1 ? l : 0.0f;
            const int i0 = (int)f0;
            w0c[k] = min(max(i0,     0), W_ - 1);
            w1c[k] = min(max(i0 + 1, 0), W_ - 1);
        }
    }

    // base pointers
    const float* __restrict__ xg = x + ((size_t)(b * C_ + g * CG_)) * HW_;
    // out[b][(g*CG_+c)*9 + kh*3+kw][ho*W_+wo]
    float* __restrict__ ob = out + (size_t)b * (C_ * K_ * K_ * (size_t)HOWO_)
                                 + (size_t)(g * CG_) * (K_ * K_) * HOWO_
                                 + (size_t)ho * W_ + wo;

    #pragma unroll 2
    for (int c = 0; c < CG_; c++) {
        const float* __restrict__ xc = xg + (size_t)c * HW_;

        // gather all 36 corners first (max MLP), then blend
        float v00[K_][K_], v01[K_][K_], v10[K_][K_], v11[K_][K_];
        #pragma unroll
        for (int kh = 0; kh < K_; kh++) {
            const float* __restrict__ r0 = xc + h0c[kh] * W_;
            const float* __restrict__ r1 = xc + h1c[kh] * W_;
            #pragma unroll
            for (int kw = 0; kw < K_; kw++) {
                v00[kh][kw] = __ldg(r0 + w0c[kw]);
                v01[kh][kw] = __ldg(r0 + w1c[kw]);
                v10[kh][kw] = __ldg(r1 + w0c[kw]);
                v11[kh][kw] = __ldg(r1 + w1c[kw]);
            }
        }

        #pragma unroll
        for (int kh = 0; kh < K_; kh++) {
            #pragma unroll
            for (int kw = 0; kw < K_; kw++) {
                const float top = bw0[kw] * v00[kh][kw] + bw1[kw] * v01[kh][kw];
                const float bot = bw0[kw] * v10[kh][kw] + bw1[kw] * v11[kh][kw];
                const float val = ah0[kh] * top + ah1[kh] * bot;
                ob[(size_t)(c * (K_ * K_) + kh * K_ + kw) * HOWO_] = val;
            }
        }
    }
}

extern "C" void kernel_launch(void* const* d_in, const int* in_sizes, int n_in,
                              void* d_out, int out_size)
{
    const float* x    = (const float*)d_in[0];
    const float* dmap = (const float*)d_in[1];
    float* out        = (float*)d_out;

    dim3 grid(H_, G_, B_);   // (ho, g, b)
    dim3 block(W_);          // wo
    ddunfold_kernel<<<grid, block>>>(x, dmap, out);
}

// round 3
// speedup vs baseline: 1.1917x; 1.1917x over previous
#include <cuda_runtime.h>
#include <cuda_fp16.h>

// DynamicDilationUnfold: B=4, C=64, H=W=128, G=4, Cg=16, K=3, pad=1, stride=1.
// Round 3: fp16 channel-quad-packed scratch + LDG.64 gathers + HFMA2 blending.
// Kernel 1 converts x (fp32 planar) -> g_scr half4 packed [b][g][c4][hw].
// Kernel 2 gathers 36 corners x 4 channel-quads per pixel, blends in half2.

#define B_   4
#define C_   64
#define H_   128
#define W_   128
#define G_   4
#define CG_  16
#define K_   3
#define HW_  (H_ * W_)          // 16384
#define NC4  4                  // channel quads per group (16/4)

// 4*4*4*16384 uint2 = 8 MB scratch (half4 per element)
__device__ uint2 g_scr[B_ * G_ * NC4 * HW_];

__device__ __forceinline__ __half2 h2lo(const uint2& v) {
    return *reinterpret_cast<const __half2*>(&v.x);
}
__device__ __forceinline__ __half2 h2hi(const uint2& v) {
    return *reinterpret_cast<const __half2*>(&v.y);
}

__global__ __launch_bounds__(256)
void convert_kernel(const float* __restrict__ x)
{
    int t = blockIdx.x * blockDim.x + threadIdx.x;   // 0 .. B*G*NC4*HW-1
    int hw = t & (HW_ - 1);
    int r  = t >> 14;          // (b*G + g)*NC4 + c4, 0..63
    int c4 = r & 3;
    int g  = (r >> 2) & 3;
    int b  = r >> 4;

    const float* xp = x + ((size_t)(b * C_ + g * CG_ + c4 * 4)) * HW_ + hw;
    float f0 = xp[0];
    float f1 = xp[HW_];
    float f2 = xp[2 * HW_];
    float f3 = xp[3 * HW_];

    __half2 lo = __floats2half2_rn(f0, f1);
    __half2 hi = __floats2half2_rn(f2, f3);
    uint2 v;
    v.x = *reinterpret_cast<unsigned int*>(&lo);
    v.y = *reinterpret_cast<unsigned int*>(&hi);
    g_scr[t] = v;
}

__global__ __launch_bounds__(128, 4)
void ddunfold_kernel(const float* __restrict__ dmap,
                     float* __restrict__ out)
{
    const int wo = threadIdx.x;          // 0..127
    const int ho = blockIdx.x;           // 0..127
    const int g  = blockIdx.y;           // 0..3
    const int b  = blockIdx.z;           // 0..3

    const float d = dmap[((b * G_ + g) * H_ + ho) * W_ + wo];

    // ---- per-pixel separable precompute (fp32 positions, half2 weights) ----
    __half2 ah0h[K_], ah1h[K_], bw0h[K_], bw1h[K_];
    int h0o[K_], h1o[K_];                // row offsets (pre-multiplied by W)
    int w0c[K_], w1c[K_];

    #pragma unroll
    for (int k = 0; k < K_; k++) {
        // h axis
        {
            const float p  = (float)(ho - 1) + (float)k * d;
            const float f0 = floorf(p);
            const float l  = p - f0;
            const bool  v0 = (f0 >= 0.0f)  && (f0 <= (float)(H_ - 1));
            const bool  v1 = (f0 >= -1.0f) && (f0 <= (float)(H_ - 2));
            ah0h[k] = __float2half2_rn(v0 ? (1.0f - l) : 0.0f);
            ah1h[k] = __float2half2_rn(v1 ? l : 0.0f);
            const int i0 = (int)f0;
            h0o[k] = min(max(i0,     0), H_ - 1) * W_;
            h1o[k] = min(max(i0 + 1, 0), H_ - 1) * W_;
        }
        // w axis
        {
            const float p  = (float)(wo - 1) + (float)k * d;
            const float f0 = floorf(p);
            const float l  = p - f0;
            const bool  v0 = (f0 >= 0.0f)  && (f0 <= (float)(W_ - 1));
            const bool  v1 = (f0 >= -1.0f) && (f0 <= (float)(W_ - 2));
            bw0h[k] = __float2half2_rn(v0 ? (1.0f - l) : 0.0f);
            bw1h[k] = __float2half2_rn(v1 ? l : 0.0f);
            const int i0 = (int)f0;
            w0c[k] = min(max(i0,     0), W_ - 1);
            w1c[k] = min(max(i0 + 1, 0), W_ - 1);
        }
    }

    const int pix = ho * W_ + wo;
    // out[((b*C + ch)*9 + tap)*HW + pix]
    float* __restrict__ ob = out
        + ((size_t)(b * C_ + g * CG_)) * (K_ * K_) * HW_ + pix;

    const uint2* __restrict__ pg =
        g_scr + ((size_t)((b * G_ + g) * NC4)) * HW_;

    #pragma unroll
    for (int c4 = 0; c4 < NC4; c4++) {
        const uint2* __restrict__ pc = pg + (size_t)c4 * HW_;
        float* __restrict__ oc = ob + (size_t)(c4 * 4) * (K_ * K_) * HW_;

        #pragma unroll
        for (int kh = 0; kh < K_; kh++) {
            const int r0 = h0o[kh];
            const int r1 = h1o[kh];

            uint2 q00[K_], q01[K_], q10[K_], q11[K_];
            #pragma unroll
            for (int kw = 0; kw < K_; kw++) {
                q00[kw] = __ldg(pc + r0 + w0c[kw]);
                q01[kw] = __ldg(pc + r0 + w1c[kw]);
                q10[kw] = __ldg(pc + r1 + w0c[kw]);
                q11[kw] = __ldg(pc + r1 + w1c[kw]);
            }

            #pragma unroll
            for (int kw = 0; kw < K_; kw++) {
                // horizontal blend (channels 0,1 in lo; 2,3 in hi)
                __half2 tl = __hfma2(bw1h[kw], h2lo(q01[kw]), __hmul2(bw0h[kw], h2lo(q00[kw])));
                __half2 th = __hfma2(bw1h[kw], h2hi(q01[kw]), __hmul2(bw0h[kw], h2hi(q00[kw])));
                __half2 bl = __hfma2(bw1h[kw], h2lo(q11[kw]), __hmul2(bw0h[kw], h2lo(q10[kw])));
                __half2 bh = __hfma2(bw1h[kw], h2hi(q11[kw]), __hmul2(bw0h[kw], h2hi(q10[kw])));
                // vertical blend
                __half2 ol = __hfma2(ah1h[kh], bl, __hmul2(ah0h[kh], tl));
                __half2 oh = __hfma2(ah1h[kh], bh, __hmul2(ah0h[kh], th));

                float2 fl = __half22float2(ol);
                float2 fh = __half22float2(oh);

                float* o0 = oc + (size_t)(kh * K_ + kw) * HW_;
                o0[0]                       = fl.x;
                o0[(size_t)1 * K_*K_ * HW_] = fl.y;
                o0[(size_t)2 * K_*K_ * HW_] = fh.x;
                o0[(size_t)3 * K_*K_ * HW_] = fh.y;
            }
        }
    }
}

extern "C" void kernel_launch(void* const* d_in, const int* in_sizes, int n_in,
                              void* d_out, int out_size)
{
    const float* x    = (const float*)d_in[0];
    const float* dmap = (const float*)d_in[1];
    float* out        = (float*)d_out;

    // Kernel 1: fp32 planar -> fp16 channel-quad packed scratch
    const int total = B_ * G_ * NC4 * HW_;           // 1,048,576
    convert_kernel<<<total / 256, 256>>>(x);

    // Kernel 2: gather + blend
    dim3 grid(H_, G_, B_);   // (ho, g, b)
    dim3 block(W_);          // wo
    ddunfold_kernel<<<grid, block>>>(dmap, out);
}

// round 5
// speedup vs baseline: 1.3774x; 1.1558x over previous
#include <cuda_runtime.h>
#include <cuda_fp16.h>

// DynamicDilationUnfold R5 (=R4 + compile fix): fp16 channel-quad scratch +
// SMEM row-tile gathers. B=4, C=64, H=W=128, G=4, Cg=16, K=3, pad=1, stride=1.

#define B_   4
#define C_   64
#define H_   128
#define W_   128
#define G_   4
#define CG_  16
#define K_   3
#define HW_  (H_ * W_)          // 16384
#define NC4  4                  // channel quads per group
#define NROW 7                  // rows ho-1 .. ho+5 (d < 3.0)
#define WP   (W_ + 1)           // padded row (bank stagger)

// 8 MB fp16 scratch: [b][g][c4][hw], half4 per element
__device__ uint2 g_scr[B_ * G_ * NC4 * HW_];

__device__ __forceinline__ __half2 h2lo(const uint2& v) {
    return *reinterpret_cast<const __half2*>(&v.x);
}
__device__ __forceinline__ __half2 h2hi(const uint2& v) {
    return *reinterpret_cast<const __half2*>(&v.y);
}
__device__ __forceinline__ unsigned int h2u(__half2 h) {
    return *reinterpret_cast<unsigned int*>(&h);
}

// fp32 planar -> fp16 quad-packed; 4 hw per thread (float4 in, uint4 out)
__global__ __launch_bounds__(256)
void convert_kernel(const float* __restrict__ x)
{
    const int t  = blockIdx.x * blockDim.x + threadIdx.x;  // 0..262143
    const int q  = t & (HW_ / 4 - 1);                      // hw/4
    const int r  = t >> 12;                                // (b*G+g)*NC4+c4
    const int c4 = r & 3;
    const int g  = (r >> 2) & 3;
    const int b  = r >> 4;

    const float4* xp = reinterpret_cast<const float4*>(
        x + ((size_t)(b * C_ + g * CG_ + c4 * 4)) * HW_) + q;
    const float4 f0 = __ldg(xp);
    const float4 f1 = __ldg(xp + HW_ / 4);
    const float4 f2 = __ldg(xp + 2 * (HW_ / 4));
    const float4 f3 = __ldg(xp + 3 * (HW_ / 4));

    uint4 o0, o1;
    o0.x = h2u(__floats2half2_rn(f0.x, f1.x));
    o0.y = h2u(__floats2half2_rn(f2.x, f3.x));
    o0.z = h2u(__floats2half2_rn(f0.y, f1.y));
    o0.w = h2u(__floats2half2_rn(f2.y, f3.y));
    o1.x = h2u(__floats2half2_rn(f0.z, f1.z));
    o1.y = h2u(__floats2half2_rn(f2.z, f3.z));
    o1.z = h2u(__floats2half2_rn(f0.w, f1.w));
    o1.w = h2u(__floats2half2_rn(f2.w, f3.w));

    uint4* dst = reinterpret_cast<uint4*>(g_scr + (size_t)r * HW_ + 4 * q);
    dst[0] = o0;
    dst[1] = o1;
}

__global__ __launch_bounds__(128, 6)
void ddunfold_kernel(const float* __restrict__ dmap,
                     float* __restrict__ out)
{
    __shared__ uint2 tile[NC4][NROW][WP];   // 28,896 B

    const int wo = threadIdx.x;          // 0..127
    const int ho = blockIdx.x;           // 0..127
    const int g  = blockIdx.y;           // 0..3
    const int b  = blockIdx.z;           // 0..3

    // ---- fill smem: 4 c4-planes x 7 rows, coalesced LDG.64 ----
    const uint2* __restrict__ pg =
        g_scr + ((size_t)((b * G_ + g) * NC4)) * HW_;
    #pragma unroll
    for (int i = 0; i < NC4 * NROW; i++) {
        const int c4 = i / NROW;
        const int j  = i - c4 * NROW;
        const int gr = min(max(ho - 1 + j, 0), H_ - 1);
        tile[c4][j][wo] = __ldg(pg + (size_t)c4 * HW_ + gr * W_ + wo);
    }

    const float d = dmap[((b * G_ + g) * H_ + ho) * W_ + wo];

    // ---- per-pixel separable precompute ----
    __half2 ah0h[K_], ah1h[K_], bw0h[K_], bw1h[K_];
    int jh0[K_], jh1[K_];                // smem row indices 0..6
    int w0c[K_], w1c[K_];

    #pragma unroll
    for (int k = 0; k < K_; k++) {
        // h axis
        {
            const float p  = (float)(ho - 1) + (float)k * d;
            const float f0 = floorf(p);
            const float l  = p - f0;
            const bool  v0 = (f0 >= 0.0f)  && (f0 <= (float)(H_ - 1));
            const bool  v1 = (f0 >= -1.0f) && (f0 <= (float)(H_ - 2));
            ah0h[k] = __float2half2_rn(v0 ? (1.0f - l) : 0.0f);
            ah1h[k] = __float2half2_rn(v1 ? l : 0.0f);
            const int j = (int)f0 - (ho - 1);     // nominal 0..5
            jh0[k] = min(max(j,     0), NROW - 1);
            jh1[k] = min(max(j + 1, 0), NROW - 1);
        }
        // w axis
        {
            const float p  = (float)(wo - 1) + (float)k * d;
            const float f0 = floorf(p);
            const float l  = p - f0;
            const bool  v0 = (f0 >= 0.0f)  && (f0 <= (float)(W_ - 1));
            const bool  v1 = (f0 >= -1.0f) && (f0 <= (float)(W_ - 2));
            bw0h[k] = __float2half2_rn(v0 ? (1.0f - l) : 0.0f);
            bw1h[k] = __float2half2_rn(v1 ? l : 0.0f);
            const int i0 = (int)f0;
            w0c[k] = min(max(i0,     0), W_ - 1);
            w1c[k] = min(max(i0 + 1, 0), W_ - 1);
        }
    }

    __syncthreads();

    const int pix = ho * W_ + wo;
    float* __restrict__ ob = out
        + ((size_t)(b * C_ + g * CG_)) * (K_ * K_) * HW_ + pix;

    #pragma unroll
    for (int c4 = 0; c4 < NC4; c4++) {
        float* __restrict__ oc = ob + (size_t)(c4 * 4) * (K_ * K_) * HW_;

        #pragma unroll
        for (int kh = 0; kh < K_; kh++) {
            const int r0 = jh0[kh];
            const int r1 = jh1[kh];

            uint2 q00[K_], q01[K_], q10[K_], q11[K_];
            #pragma unroll
            for (int kw = 0; kw < K_; kw++) {
                q00[kw] = tile[c4][r0][w0c[kw]];
                q01[kw] = tile[c4][r0][w1c[kw]];
                q10[kw] = tile[c4][r1][w0c[kw]];
                q11[kw] = tile[c4][r1][w1c[kw]];
            }

            #pragma unroll
            for (int kw = 0; kw < K_; kw++) {
                __half2 tl = __hfma2(bw1h[kw], h2lo(q01[kw]), __hmul2(bw0h[kw], h2lo(q00[kw])));
                __half2 th = __hfma2(bw1h[kw], h2hi(q01[kw]), __hmul2(bw0h[kw], h2hi(q00[kw])));
                __half2 bl = __hfma2(bw1h[kw], h2lo(q11[kw]), __hmul2(bw0h[kw], h2lo(q10[kw])));
                __half2 bh = __hfma2(bw1h[kw], h2hi(q11[kw]), __hmul2(bw0h[kw], h2hi(q10[kw])));
                __half2 ol = __hfma2(ah1h[kh], bl, __hmul2(ah0h[kh], tl));
                __half2 oh = __hfma2(ah1h[kh], bh, __hmul2(ah0h[kh], th));

                const float2 fl = __half22float2(ol);
                const float2 fh = __half22float2(oh);

                float* o0 = oc + (size_t)(kh * K_ + kw) * HW_;
                o0[0]                         = fl.x;
                o0[(size_t)1 * K_ * K_ * HW_] = fl.y;
                o0[(size_t)2 * K_ * K_ * HW_] = fh.x;
                o0[(size_t)3 * K_ * K_ * HW_] = fh.y;
            }
        }
    }
}

extern "C" void kernel_launch(void* const* d_in, const int* in_sizes, int n_in,
                              void* d_out, int out_size)
{
    const float* x    = (const float*)d_in[0];
    const float* dmap = (const float*)d_in[1];
    float* out        = (float*)d_out;

    convert_kernel<<<(B_ * G_ * NC4 * HW_ / 4) / 256, 256>>>(x);

    dim3 grid(H_, G_, B_);   // (ho, g, b)
    dim3 block(W_);          // wo
    ddunfold_kernel<<<grid, block>>>(dmap, out);
}

// round 6
// speedup vs baseline: 1.5371x; 1.1159x over previous
#include <cuda_runtime.h>
#include <cuda_fp16.h>

// DynamicDilationUnfold R6: single fused kernel.
// fp32 x -> (convert to half4-packed during smem fill) -> SMEM row-tile
// gathers -> HFMA2 blend -> fp32 stores.
// Block: 256 threads = 2 output rows x 128 wo. 8-row halo, 4 channel-quads.
// B=4, C=64, H=W=128, G=4, Cg=16, K=3, pad=1, stride=1.

#define B_    4
#define C_    64
#define H_    128
#define W_    128
#define G_    4
#define CG_   16
#define K_    3
#define HW_   (H_ * W_)          // 16384
#define NC4   4                  // channel quads per group
#define NROWS 8                  // rows hb-1 .. hb+6 (2 out rows, d < 3.0)
#define WP    (W_ + 1)           // padded row (bank stagger)

__device__ __forceinline__ __half2 h2lo(const uint2& v) {
    return *reinterpret_cast<const __half2*>(&v.x);
}
__device__ __forceinline__ __half2 h2hi(const uint2& v) {
    return *reinterpret_cast<const __half2*>(&v.y);
}
__device__ __forceinline__ unsigned int h2u(__half2 h) {
    return *reinterpret_cast<unsigned int*>(&h);
}

__global__ __launch_bounds__(256, 4)
void ddunfold_kernel(const float* __restrict__ x,
                     const float* __restrict__ dmap,
                     float* __restrict__ out)
{
    __shared__ uint2 tile[NC4][NROWS][WP];   // 33,024 B

    const int wo = threadIdx.x & (W_ - 1);   // 0..127
    const int ty = threadIdx.x >> 7;         // 0/1: which output row
    const int hb = blockIdx.x << 1;          // ho base (even)
    const int g  = blockIdx.y;               // 0..3
    const int b  = blockIdx.z;               // 0..3

    // ---- fused fill: fp32 planar -> half4 quad-packed smem rows ----
    const float* __restrict__ xg = x + (size_t)(b * C_ + g * CG_) * HW_;
    #pragma unroll
    for (int i = 0; i < 16; i++) {
        const int combo = 2 * i + ty;        // 0..31
        const int c4 = combo >> 3;
        const int j  = combo & 7;
        const int gr = min(max(hb - 1 + j, 0), H_ - 1);
        const float* xp = xg + (size_t)(c4 * 4) * HW_ + gr * W_ + wo;
        const float f0 = __ldg(xp);
        const float f1 = __ldg(xp + HW_);
        const float f2 = __ldg(xp + 2 * HW_);
        const float f3 = __ldg(xp + 3 * HW_);
        uint2 v;
        v.x = h2u(__floats2half2_rn(f0, f1));
        v.y = h2u(__floats2half2_rn(f2, f3));
        tile[c4][j][wo] = v;
    }

    const int ho = hb + ty;
    const float d = dmap[((b * G_ + g) * H_ + ho) * W_ + wo];

    // ---- per-pixel separable precompute ----
    __half2 ah0h[K_], ah1h[K_], bw0h[K_], bw1h[K_];
    int jh0[K_], jh1[K_];                // smem row indices 0..7
    int w0c[K_], w1c[K_];

    #pragma unroll
    for (int k = 0; k < K_; k++) {
        // h axis
        {
            const float p  = (float)(ho - 1) + (float)k * d;
            const float f0 = floorf(p);
            const float l  = p - f0;
            const bool  v0 = (f0 >= 0.0f)  && (f0 <= (float)(H_ - 1));
            const bool  v1 = (f0 >= -1.0f) && (f0 <= (float)(H_ - 2));
            ah0h[k] = __float2half2_rn(v0 ? (1.0f - l) : 0.0f);
            ah1h[k] = __float2half2_rn(v1 ? l : 0.0f);
            const int j = (int)f0 - (hb - 1);    // nominal ty..ty+5
            jh0[k] = min(max(j,     0), NROWS - 1);
            jh1[k] = min(max(j + 1, 0), NROWS - 1);
        }
        // w axis
        {
            const float p  = (float)(wo - 1) + (float)k * d;
            const float f0 = floorf(p);
            const float l  = p - f0;
            const bool  v0 = (f0 >= 0.0f)  && (f0 <= (float)(W_ - 1));
            const bool  v1 = (f0 >= -1.0f) && (f0 <= (float)(W_ - 2));
            bw0h[k] = __float2half2_rn(v0 ? (1.0f - l) : 0.0f);
            bw1h[k] = __float2half2_rn(v1 ? l : 0.0f);
            const int i0 = (int)f0;
            w0c[k] = min(max(i0,     0), W_ - 1);
            w1c[k] = min(max(i0 + 1, 0), W_ - 1);
        }
    }

    __syncthreads();

    const int pix = ho * W_ + wo;
    float* __restrict__ ob = out
        + ((size_t)(b * C_ + g * CG_)) * (K_ * K_) * HW_ + pix;

    #pragma unroll
    for (int c4 = 0; c4 < NC4; c4++) {
        float* __restrict__ oc = ob + (size_t)(c4 * 4) * (K_ * K_) * HW_;

        #pragma unroll
        for (int kh = 0; kh < K_; kh++) {
            const int r0 = jh0[kh];
            const int r1 = jh1[kh];

            #pragma unroll
            for (int kw = 0; kw < K_; kw++) {
                const uint2 q00 = tile[c4][r0][w0c[kw]];
                const uint2 q01 = tile[c4][r0][w1c[kw]];
                const uint2 q10 = tile[c4][r1][w0c[kw]];
                const uint2 q11 = tile[c4][r1][w1c[kw]];

                __half2 tl = __hfma2(bw1h[kw], h2lo(q01), __hmul2(bw0h[kw], h2lo(q00)));
                __half2 th = __hfma2(bw1h[kw], h2hi(q01), __hmul2(bw0h[kw], h2hi(q00)));
                __half2 bl = __hfma2(bw1h[kw], h2lo(q11), __hmul2(bw0h[kw], h2lo(q10)));
                __half2 bh = __hfma2(bw1h[kw], h2hi(q11), __hmul2(bw0h[kw], h2hi(q10)));
                __half2 ol = __hfma2(ah1h[kh], bl, __hmul2(ah0h[kh], tl));
                __half2 oh = __hfma2(ah1h[kh], bh, __hmul2(ah0h[kh], th));

                const float2 fl = __half22float2(ol);
                const float2 fh = __half22float2(oh);

                float* o0 = oc + (size_t)(kh * K_ + kw) * HW_;
                o0[0]                         = fl.x;
                o0[(size_t)1 * K_ * K_ * HW_] = fl.y;
                o0[(size_t)2 * K_ * K_ * HW_] = fh.x;
                o0[(size_t)3 * K_ * K_ * HW_] = fh.y;
            }
        }
    }
}

extern "C" void kernel_launch(void* const* d_in, const int* in_sizes, int n_in,
                              void* d_out, int out_size)
{
    const float* x    = (const float*)d_in[0];
    const float* dmap = (const float*)d_in[1];
    float* out        = (float*)d_out;

    dim3 grid(H_ / 2, G_, B_);   // (ho pair, g, b)
    dim3 block(256);             // 2 rows x 128 wo
    ddunfold_kernel<<<grid, block>>>(x, dmap, out);
}

// round 7
// speedup vs baseline: 1.6302x; 1.0605x over previous
#include <cuda_runtime.h>
#include <cuda_fp16.h>

// DynamicDilationUnfold R7: fused kernel + k=0 integer-tap specialization.
// Tap k=0 positions are exact integers (out-1), so tap (0,0) is a copy,
// taps (0,kw)/(kh,0) are 1-D lerps, only 4 taps need full bilinear.
// B=4, C=64, H=W=128, G=4, Cg=16, K=3, pad=1, stride=1.

#define B_    4
#define C_    64
#define H_    128
#define W_    128
#define G_    4
#define CG_   16
#define HW_   (H_ * W_)          // 16384
#define NC4   4                  // channel quads per group
#define NROWS 8                  // rows hb-1 .. hb+6 (2 out rows, d < 3.0)
#define WP    (W_ + 1)           // padded row (bank stagger)
#define TT    9                  // taps per channel
#define CS    (TT * HW_)         // out channel stride

__device__ __forceinline__ __half2 h2lo(const uint2& v) {
    return *reinterpret_cast<const __half2*>(&v.x);
}
__device__ __forceinline__ __half2 h2hi(const uint2& v) {
    return *reinterpret_cast<const __half2*>(&v.y);
}
__device__ __forceinline__ unsigned int h2u(__half2 h) {
    return *reinterpret_cast<unsigned int*>(&h);
}

__device__ __forceinline__ void st4(float* o, int tap, __half2 lo, __half2 hi)
{
    const float2 fl = __half22float2(lo);
    const float2 fh = __half22float2(hi);
    float* p = o + (size_t)tap * HW_;
    p[0]              = fl.x;
    p[(size_t)1 * CS] = fl.y;
    p[(size_t)2 * CS] = fh.x;
    p[(size_t)3 * CS] = fh.y;
}

__global__ __launch_bounds__(256, 4)
void ddunfold_kernel(const float* __restrict__ x,
                     const float* __restrict__ dmap,
                     float* __restrict__ out)
{
    __shared__ uint2 tile[NC4][NROWS][WP];   // 33,024 B

    const int wo = threadIdx.x & (W_ - 1);   // 0..127
    const int ty = threadIdx.x >> 7;         // 0/1: which output row
    const int hb = blockIdx.x << 1;          // ho base (even)
    const int g  = blockIdx.y;               // 0..3
    const int b  = blockIdx.z;               // 0..3

    // ---- fused fill: fp32 planar -> half4 quad-packed smem rows ----
    const float* __restrict__ xg = x + (size_t)(b * C_ + g * CG_) * HW_;
    #pragma unroll
    for (int i = 0; i < 16; i++) {
        const int combo = 2 * i + ty;        // 0..31
        const int c4 = combo >> 3;
        const int j  = combo & 7;
        const int gr = min(max(hb - 1 + j, 0), H_ - 1);
        const float* xp = xg + (size_t)(c4 * 4) * HW_ + gr * W_ + wo;
        const float f0 = __ldg(xp);
        const float f1 = __ldg(xp + HW_);
        const float f2 = __ldg(xp + 2 * HW_);
        const float f3 = __ldg(xp + 3 * HW_);
        uint2 v;
        v.x = h2u(__floats2half2_rn(f0, f1));
        v.y = h2u(__floats2half2_rn(f2, f3));
        tile[c4][j][wo] = v;
    }

    const int ho = hb + ty;
    const float d = dmap[((b * G_ + g) * H_ + ho) * W_ + wo];

    // ---- k=0: exact integer tap at (ho-1, wo-1) ----
    const __half2 mh0 = __float2half2_rn(ho >= 1 ? 1.0f : 0.0f);
    const __half2 mw0 = __float2half2_rn(wo >= 1 ? 1.0f : 0.0f);
    const __half2 m00 = __hmul2(mh0, mw0);
    const int wm1 = max(wo - 1, 0);

    // ---- k=1,2: separable weights + smem indices ----
    __half2 ah0h[2], ah1h[2], bw0h[2], bw1h[2];   // raw (for full taps)
    __half2 ah0m[2], ah1m[2], bw0m[2], bw1m[2];   // masked (for edge taps)
    int jh0[2], jh1[2], w0c[2], w1c[2];

    #pragma unroll
    for (int kk = 0; kk < 2; kk++) {
        const float kf = (float)(kk + 1);
        // h axis
        {
            const float p  = (float)(ho - 1) + kf * d;
            const float f0 = floorf(p);
            const float l  = p - f0;
            const bool  v0 = (f0 >= 0.0f)  && (f0 <= (float)(H_ - 1));
            const bool  v1 = (f0 >= -1.0f) && (f0 <= (float)(H_ - 2));
            ah0h[kk] = __float2half2_rn(v0 ? (1.0f - l) : 0.0f);
            ah1h[kk] = __float2half2_rn(v1 ? l : 0.0f);
            const int j = (int)f0 - (hb - 1);
            jh0[kk] = min(max(j,     0), NROWS - 1);
            jh1[kk] = min(max(j + 1, 0), NROWS - 1);
        }
        // w axis
        {
            const float p  = (float)(wo - 1) + kf * d;
            const float f0 = floorf(p);
            const float l  = p - f0;
            const bool  v0 = (f0 >= 0.0f)  && (f0 <= (float)(W_ - 1));
            const bool  v1 = (f0 >= -1.0f) && (f0 <= (float)(W_ - 2));
            bw0h[kk] = __float2half2_rn(v0 ? (1.0f - l) : 0.0f);
            bw1h[kk] = __float2half2_rn(v1 ? l : 0.0f);
            const int i0 = (int)f0;
            w0c[kk] = min(max(i0,     0), W_ - 1);
            w1c[kk] = min(max(i0 + 1, 0), W_ - 1);
        }
        ah0m[kk] = __hmul2(mw0, ah0h[kk]);
        ah1m[kk] = __hmul2(mw0, ah1h[kk]);
        bw0m[kk] = __hmul2(mh0, bw0h[kk]);
        bw1m[kk] = __hmul2(mh0, bw1h[kk]);
    }

    __syncthreads();

    const int pix = ho * W_ + wo;
    float* __restrict__ ob = out + ((size_t)(b * C_ + g * CG_)) * CS + pix;

    #pragma unroll
    for (int c4 = 0; c4 < NC4; c4++) {
        float* __restrict__ oc = ob + (size_t)(c4 * 4) * CS;

        // tap (0,0): direct copy with border mask
        {
            const uint2 q = tile[c4][ty][wm1];
            st4(oc, 0, __hmul2(m00, h2lo(q)), __hmul2(m00, h2hi(q)));
        }

        // taps (0,kw), kw=1,2: horizontal lerp on row ho-1
        #pragma unroll
        for (int kk = 0; kk < 2; kk++) {
            const uint2 q0 = tile[c4][ty][w0c[kk]];
            const uint2 q1 = tile[c4][ty][w1c[kk]];
            const __half2 lo = __hfma2(bw1m[kk], h2lo(q1), __hmul2(bw0m[kk], h2lo(q0)));
            const __half2 hi = __hfma2(bw1m[kk], h2hi(q1), __hmul2(bw0m[kk], h2hi(q0)));
            st4(oc, kk + 1, lo, hi);
        }

        // taps (kh,0), kh=1,2: vertical lerp on col wo-1
        #pragma unroll
        for (int kk = 0; kk < 2; kk++) {
            const uint2 q0 = tile[c4][jh0[kk]][wm1];
            const uint2 q1 = tile[c4][jh1[kk]][wm1];
            const __half2 lo = __hfma2(ah1m[kk], h2lo(q1), __hmul2(ah0m[kk], h2lo(q0)));
            const __half2 hi = __hfma2(ah1m[kk], h2hi(q1), __hmul2(ah0m[kk], h2hi(q0)));
            st4(oc, (kk + 1) * 3, lo, hi);
        }

        // full bilinear taps (kh,kw), kh,kw in {1,2}
        #pragma unroll
        for (int kh = 0; kh < 2; kh++) {
            const int r0 = jh0[kh];
            const int r1 = jh1[kh];
            #pragma unroll
            for (int kw = 0; kw < 2; kw++) {
                const uint2 q00 = tile[c4][r0][w0c[kw]];
                const uint2 q01 = tile[c4][r0][w1c[kw]];
                const uint2 q10 = tile[c4][r1][w0c[kw]];
                const uint2 q11 = tile[c4][r1][w1c[kw]];

                const __half2 tl = __hfma2(bw1h[kw], h2lo(q01), __hmul2(bw0h[kw], h2lo(q00)));
                const __half2 th = __hfma2(bw1h[kw], h2hi(q01), __hmul2(bw0h[kw], h2hi(q00)));
                const __half2 bl = __hfma2(bw1h[kw], h2lo(q11), __hmul2(bw0h[kw], h2lo(q10)));
                const __half2 bh = __hfma2(bw1h[kw], h2hi(q11), __hmul2(bw0h[kw], h2hi(q10)));
                const __half2 ol = __hfma2(ah1h[kh], bl, __hmul2(ah0h[kh], tl));
                const __half2 oh = __hfma2(ah1h[kh], bh, __hmul2(ah0h[kh], th));

                st4(oc, (kh + 1) * 3 + (kw + 1), ol, oh);
            }
        }
    }
}

extern "C" void kernel_launch(void* const* d_in, const int* in_sizes, int n_in,
                              void* d_out, int out_size)
{
    const float* x    = (const float*)d_in[0];
    const float* dmap = (const float*)d_in[1];
    float* out        = (float*)d_out;

    dim3 grid(H_ / 2, G_, B_);   // (ho pair, g, b)
    dim3 block(256);             // 2 rows x 128 wo
    ddunfold_kernel<<<grid, block>>>(x, dmap, out);
}